// round 1
// baseline (speedup 1.0000x reference)
#include <cuda_runtime.h>
#include <cuda_bf16.h>
#include <cstdint>

// Problem dims (fixed by the reference setup)
#define NB 64
#define CH 32
#define HH 128
#define WW 128
#define OD 4096
#define PIX (HH*WW)   // 16384

// 5x5 Gaussian filter
__constant__ float c_f[5][5] = {
    {0.003765f, 0.015019f, 0.023792f, 0.015019f, 0.003765f},
    {0.015019f, 0.059912f, 0.094907f, 0.059912f, 0.015019f},
    {0.023792f, 0.094907f, 0.150342f, 0.094907f, 0.023792f},
    {0.015019f, 0.059912f, 0.094907f, 0.059912f, 0.015019f},
    {0.003765f, 0.015019f, 0.023792f, 0.015019f, 0.003765f}
};

// Scratch: NHWC pyramid buffers (static device allocations are allowed)
static __device__ float g_xt [ (size_t)NB*128*128*CH ];  // x transposed to NHWC
static __device__ float g_hi0[ (size_t)NB*128*128*CH ];
static __device__ float g_lo0[ (size_t)NB* 64* 64*CH ];
static __device__ float g_hi1[ (size_t)NB* 64* 64*CH ];
static __device__ float g_lo1[ (size_t)NB* 32* 32*CH ];
static __device__ float g_hi2[ (size_t)NB* 32* 32*CH ];
static __device__ float g_lo2[ (size_t)NB* 16* 16*CH ];
static __device__ float g_hi3[ (size_t)NB* 16* 16*CH ];
static __device__ float g_lo3[ (size_t)NB*  8*  8*CH ];

// ---------------------------------------------------------------------------
// Transpose: x (N,C,H,W) -> g_xt (N,H*W,C)
// ---------------------------------------------------------------------------
__global__ __launch_bounds__(256) void k_transpose(const float* __restrict__ x) {
    __shared__ float tile[32][33];
    const int n  = blockIdx.y;
    const int p0 = blockIdx.x * 32;
    const int tx = threadIdx.x;           // 0..31
    const int ty = threadIdx.y;           // 0..7

    // read: lanes along p (coalesced), rows = channel
    #pragma unroll
    for (int r = ty; r < 32; r += 8)
        tile[r][tx] = x[((size_t)(n*CH + r))*PIX + p0 + tx];
    __syncthreads();
    // write: lanes along channel (coalesced)
    #pragma unroll
    for (int r = ty; r < 32; r += 8)
        g_xt[((size_t)n*PIX + p0 + r)*CH + tx] = tile[tx][r];
}

// ---------------------------------------------------------------------------
// Level helpers (compile-time pointer selection)
// ---------------------------------------------------------------------------
template<int L> __device__ __forceinline__ const float* img_of() {
    if (L == 0) return g_xt;
    if (L == 1) return g_lo0;
    if (L == 2) return g_lo1;
    return g_lo2;
}
template<int L> __device__ __forceinline__ float* lo_of() {
    if (L == 0) return g_lo0;
    if (L == 1) return g_lo1;
    if (L == 2) return g_lo2;
    return g_lo3;
}
template<int L> __device__ __forceinline__ float* hi_of() {
    if (L == 0) return g_hi0;
    if (L == 1) return g_hi1;
    if (L == 2) return g_hi2;
    return g_hi3;
}

// ---------------------------------------------------------------------------
// Downsample: lo[i,j] = 5x5 gaussian of img at (2i,2j), zero-padded
// NHWC, lane = channel. S = input size (per side), Sl = S/2.
// ---------------------------------------------------------------------------
template<int L>
__global__ __launch_bounds__(256) void k_down() {
    constexpr int S  = 128 >> L;
    constexpr int Sl = S / 2;
    const int ch = threadIdx.x;
    const int j  = blockIdx.x * 8 + threadIdx.y;
    const int i  = blockIdx.y;
    const int n  = blockIdx.z;
    if (j >= Sl) return;

    const float* img = img_of<L>() + (size_t)n * S * S * CH;
    float acc = 0.f;
    #pragma unroll
    for (int ky = 0; ky < 5; ky++) {
        const int t = 2*i + ky - 2;
        if (t < 0 || t >= S) continue;
        #pragma unroll
        for (int kx = 0; kx < 5; kx++) {
            const int s = 2*j + kx - 2;
            if (s < 0 || s >= S) continue;
            acc += c_f[ky][kx] * img[((size_t)t*S + s)*CH + ch];
        }
    }
    lo_of<L>()[(((size_t)n*Sl + i)*Sl + j)*CH + ch] = acc;
}

// ---------------------------------------------------------------------------
// Laplacian: hi[y,x] = img[y,x] - 4 * upconv(lo)[y,x]
// upconv taps: f[ky,kx]*lo[(y+ky-2)/2,(x+kx-2)/2] where (y+ky-2) even & in range
// ---------------------------------------------------------------------------
template<int L>
__global__ __launch_bounds__(256) void k_hi() {
    constexpr int S  = 128 >> L;
    constexpr int Sl = S / 2;
    const int ch = threadIdx.x;
    const int x  = blockIdx.x * 8 + threadIdx.y;
    const int y  = blockIdx.y;
    const int n  = blockIdx.z;
    if (x >= S) return;

    const float* lo = lo_of<L>() + (size_t)n * Sl * Sl * CH;
    float acc = 0.f;
    #pragma unroll
    for (int ky = 0; ky < 5; ky++) {
        const int t = y + ky - 2;
        if (t < 0 || (t & 1)) continue;
        const int i = t >> 1;
        if (i >= Sl) continue;
        #pragma unroll
        for (int kx = 0; kx < 5; kx++) {
            const int s = x + kx - 2;
            if (s < 0 || (s & 1)) continue;
            const int jj = s >> 1;
            if (jj >= Sl) continue;
            acc += c_f[ky][kx] * lo[((size_t)i*Sl + jj)*CH + ch];
        }
    }
    const size_t idx = (((size_t)n*S + y)*S + x)*CH + ch;
    hi_of<L>()[idx] = img_of<L>()[idx] - 4.f * acc;
}

// ---------------------------------------------------------------------------
// Sample + weighted channel reduction
// block = (n, 32-wide o-tile). 8 warps, each warp covers 4 o's, lane = channel.
// ---------------------------------------------------------------------------
__device__ __forceinline__ const float* level_ptr(int l) {
    switch (l) {
        case 0: return g_hi0;
        case 1: return g_hi1;
        case 2: return g_hi2;
        case 3: return g_hi3;
        default: return g_lo3;
    }
}

__global__ __launch_bounds__(256) void k_sample(const float* __restrict__ grid,
                                                const float* __restrict__ feat,
                                                const float* __restrict__ bias,
                                                float* __restrict__ out) {
    __shared__ float featS[160][33];
    const int tid  = threadIdx.x;
    const int o0   = blockIdx.x * 32;
    const int n    = blockIdx.y;
    const int lane = tid & 31;
    const int warp = tid >> 5;

    // stage features tile (coalesced: lanes along o)
    for (int idx = tid; idx < 160*32; idx += 256) {
        const int row = idx >> 5;
        const int ol  = idx & 31;
        featS[row][ol] = feat[(size_t)row*OD + o0 + ol];
    }
    __syncthreads();

    for (int ol = warp; ol < 32; ol += 8) {
        const int o = o0 + ol;
        const float xs = fminf(fmaxf(grid[2*o    ], -1.f), 1.f);
        const float ys = fminf(fmaxf(grid[2*o + 1], -1.f), 1.f);
        float acc = 0.f;

        #pragma unroll
        for (int l = 0; l < 5; l++) {
            const int S = 128 >> l;                // 128,64,32,16,8
            const float* imgp = level_ptr(l);
            const float fx = ((xs + 1.f) * (float)S - 1.f) * 0.5f;
            const float fy = ((ys + 1.f) * (float)S - 1.f) * 0.5f;
            const float x0f = floorf(fx), y0f = floorf(fy);
            const float wx = fx - x0f, wy = fy - y0f;
            const int x0 = (int)x0f, y0 = (int)y0f;
            const float fv = featS[l*32 + lane][ol];

            #pragma unroll
            for (int cy = 0; cy < 2; cy++) {
                #pragma unroll
                for (int cx = 0; cx < 2; cx++) {
                    const int xc = x0 + cx;
                    const int yc = y0 + cy;
                    const float wgt = (cx ? wx : 1.f - wx) * (cy ? wy : 1.f - wy);
                    if (xc >= 0 && xc < S && yc >= 0 && yc < S) {
                        const float v = imgp[(((size_t)n*S + yc)*S + xc)*CH + lane];
                        acc += v * wgt * fv;
                    }
                }
            }
        }
        // warp reduce over channels
        #pragma unroll
        for (int off = 16; off; off >>= 1)
            acc += __shfl_xor_sync(0xFFFFFFFFu, acc, off);
        if (lane == 0)
            out[(size_t)n*OD + o] = acc + bias[o];
    }
}

// ---------------------------------------------------------------------------
// Launch
// ---------------------------------------------------------------------------
extern "C" void kernel_launch(void* const* d_in, const int* in_sizes, int n_in,
                              void* d_out, int out_size) {
    const float* x    = (const float*)d_in[0];
    const float* grid = (const float*)d_in[1];
    const float* feat = (const float*)d_in[2];
    const float* bias = (const float*)d_in[3];
    float* out = (float*)d_out;

    dim3 b(32, 8);

    // transpose x -> NHWC
    k_transpose<<<dim3(PIX/32, NB), b>>>(x);

    // pyramid
    k_down<0><<<dim3( 64/8, 64, NB), b>>>();
    k_hi  <0><<<dim3(128/8,128, NB), b>>>();
    k_down<1><<<dim3( 32/8, 32, NB), b>>>();
    k_hi  <1><<<dim3( 64/8, 64, NB), b>>>();
    k_down<2><<<dim3( 16/8, 16, NB), b>>>();
    k_hi  <2><<<dim3( 32/8, 32, NB), b>>>();
    k_down<3><<<dim3(    1,  8, NB), b>>>();
    k_hi  <3><<<dim3( 16/8, 16, NB), b>>>();

    // sample + reduce
    k_sample<<<dim3(OD/32, NB), 256>>>(grid, feat, bias, out);
}

// round 3
// speedup vs baseline: 1.2425x; 1.2425x over previous
#include <cuda_runtime.h>
#include <cuda_bf16.h>
#include <cstdint>

#define NB 64
#define CH 32
#define OD 4096
#define PIX (128*128)

// Gaussian 5x5 — __device__ constexpr so compile-time-indexed uses fold to immediates
__device__ constexpr float CF[5][5] = {
    {0.003765f, 0.015019f, 0.023792f, 0.015019f, 0.003765f},
    {0.015019f, 0.059912f, 0.094907f, 0.059912f, 0.015019f},
    {0.023792f, 0.094907f, 0.150342f, 0.094907f, 0.023792f},
    {0.015019f, 0.059912f, 0.094907f, 0.059912f, 0.015019f},
    {0.003765f, 0.015019f, 0.023792f, 0.015019f, 0.003765f}
};
__constant__ float c_f[5][5] = {
    {0.003765f, 0.015019f, 0.023792f, 0.015019f, 0.003765f},
    {0.015019f, 0.059912f, 0.094907f, 0.059912f, 0.015019f},
    {0.023792f, 0.094907f, 0.150342f, 0.094907f, 0.023792f},
    {0.015019f, 0.059912f, 0.094907f, 0.059912f, 0.015019f},
    {0.003765f, 0.015019f, 0.023792f, 0.015019f, 0.003765f}
};

// NHWC scratch (16B aligned for float4)
static __device__ __align__(256) float g_xt  [(size_t)NB*128*128*CH];
static __device__ __align__(256) float g_hi0 [(size_t)NB*128*128*CH];
static __device__ __align__(256) float g_lo0 [(size_t)NB* 64* 64*CH];
static __device__ __align__(256) float g_hi1 [(size_t)NB* 64* 64*CH];
static __device__ __align__(256) float g_lo1 [(size_t)NB* 32* 32*CH];
static __device__ __align__(256) float g_hi2 [(size_t)NB* 32* 32*CH];
static __device__ __align__(256) float g_lo2 [(size_t)NB* 16* 16*CH];
static __device__ __align__(256) float g_hi3 [(size_t)NB* 16* 16*CH];
static __device__ __align__(256) float g_lo3 [(size_t)NB*  8*  8*CH];
static __device__ __align__(256) float g_featT[(size_t)OD*160];

__device__ __forceinline__ void fma4(float4& a, float w, float4 v) {
    a.x = fmaf(w, v.x, a.x); a.y = fmaf(w, v.y, a.y);
    a.z = fmaf(w, v.z, a.z); a.w = fmaf(w, v.w, a.w);
}

// ---------------------------------------------------------------------------
// x (N,C,H,W) -> g_xt (N,H*W,C)
// ---------------------------------------------------------------------------
__global__ __launch_bounds__(256) void k_transpose(const float* __restrict__ x) {
    __shared__ float tile[32][33];
    const int n  = blockIdx.y;
    const int p0 = blockIdx.x * 32;
    const int tx = threadIdx.x, ty = threadIdx.y;
    #pragma unroll
    for (int r = ty; r < 32; r += 8)
        tile[r][tx] = x[((size_t)(n*CH + r))*PIX + p0 + tx];
    __syncthreads();
    #pragma unroll
    for (int r = ty; r < 32; r += 8)
        g_xt[((size_t)n*PIX + p0 + r)*CH + tx] = tile[tx][r];
}

// ---------------------------------------------------------------------------
// feat (160, OD) -> featT (OD, 160)
// ---------------------------------------------------------------------------
__global__ __launch_bounds__(256) void k_featT(const float* __restrict__ feat) {
    __shared__ float tile[32][33];
    const int o0 = blockIdx.x * 32;
    const int r0 = blockIdx.y * 32;
    const int tx = threadIdx.x, ty = threadIdx.y;
    #pragma unroll
    for (int r = ty; r < 32; r += 8)
        if (r0 + r < 160) tile[r][tx] = feat[(size_t)(r0 + r)*OD + o0 + tx];
    __syncthreads();
    #pragma unroll
    for (int r = ty; r < 32; r += 8)
        if (r0 + tx < 160) g_featT[(size_t)(o0 + r)*160 + r0 + tx] = tile[tx][r];
}

// ---------------------------------------------------------------------------
template<int L> __device__ __forceinline__ const float* img_of() {
    if (L == 0) return g_xt;
    if (L == 1) return g_lo0;
    if (L == 2) return g_lo1;
    return g_lo2;
}
template<int L> __device__ __forceinline__ float* lo_of() {
    if (L == 0) return g_lo0;
    if (L == 1) return g_lo1;
    if (L == 2) return g_lo2;
    return g_lo3;
}
template<int L> __device__ __forceinline__ float* hi_of() {
    if (L == 0) return g_hi0;
    if (L == 1) return g_hi1;
    if (L == 2) return g_hi2;
    return g_hi3;
}

// ---------------------------------------------------------------------------
// Downsample (float4 over channels): lo[i,j] = 5x5 @ (2i,2j)
// block (8 c4, 32 j), grid (ceil(Sl/32), Sl(i), NB)
// ---------------------------------------------------------------------------
template<int L>
__global__ __launch_bounds__(256) void k_down4() {
    constexpr int S  = 128 >> L;
    constexpr int Sl = S / 2;
    const int c4 = threadIdx.x;
    const int j  = blockIdx.x * 32 + threadIdx.y;
    const int i  = blockIdx.y;
    const int n  = blockIdx.z;
    if (j >= Sl) return;

    const float4* img = (const float4*)img_of<L>() + (size_t)n * S * S * (CH/4);
    float4 acc = make_float4(0.f, 0.f, 0.f, 0.f);

    const bool interior = (i >= 1) & (i <= Sl-2) & (j >= 1) & (j <= Sl-2);
    if (interior) {
        const float4* p = img + ((2*i-2)*S + (2*j-2))*(CH/4) + c4;
        #pragma unroll
        for (int ky = 0; ky < 5; ky++)
            #pragma unroll
            for (int kx = 0; kx < 5; kx++)
                fma4(acc, CF[ky][kx], p[(ky*S + kx)*(CH/4)]);
    } else {
        #pragma unroll
        for (int ky = 0; ky < 5; ky++) {
            const int t = 2*i + ky - 2;
            if ((unsigned)t >= (unsigned)S) continue;
            #pragma unroll
            for (int kx = 0; kx < 5; kx++) {
                const int s = 2*j + kx - 2;
                if ((unsigned)s >= (unsigned)S) continue;
                fma4(acc, c_f[ky][kx], img[(t*S + s)*(CH/4) + c4]);
            }
        }
    }
    ((float4*)lo_of<L>())[(((size_t)n*Sl + i)*Sl + j)*(CH/4) + c4] = acc;
}

// ---------------------------------------------------------------------------
// Laplacian (float4, parity-specialized): hi = img - 4*upconv(lo)
// block (8 c4, 32 x), grid (ceil(S/32), S(y), NB)
// ---------------------------------------------------------------------------
template<int L>
__global__ __launch_bounds__(256) void k_hi4() {
    constexpr int S  = 128 >> L;
    constexpr int Sl = S / 2;
    constexpr int CQ = CH / 4;
    const int c4 = threadIdx.x;
    const int x  = blockIdx.x * 32 + threadIdx.y;
    const int y  = blockIdx.y;
    const int n  = blockIdx.z;
    if (x >= S) return;

    const float4* lo = (const float4*)lo_of<L>() + (size_t)n * Sl * Sl * CQ;
    const int py = y & 1, px = x & 1;
    const int nx = 3 - px;
    const int i0 = (y - 2 + py) >> 1;
    const int j0 = (x - 2 + px) >> 1;
    float4 acc = make_float4(0.f, 0.f, 0.f, 0.f);

    const bool interior = (y >= 2) & (y <= S-3) & (x >= 2) & (x <= S-3);
    if (interior) {
        const float4* base = lo + (i0*Sl + j0)*CQ + c4;
        if (py == 0) {   // uniform branch (y fixed per block row): ky = {0,2,4}
            #pragma unroll
            for (int a = 0; a < 3; a++) {
                const float4* p = base + a*Sl*CQ;
                #pragma unroll
                for (int b = 0; b < 3; b++) {
                    const float w = px ? CF[2*a][(2*b+1 > 4) ? 4 : 2*b+1]
                                       : CF[2*a][2*b];
                    if (b < nx) fma4(acc, w, p[b*CQ]);
                }
            }
        } else {          // ky = {1,3}
            #pragma unroll
            for (int a = 0; a < 2; a++) {
                const float4* p = base + a*Sl*CQ;
                #pragma unroll
                for (int b = 0; b < 3; b++) {
                    const float w = px ? CF[2*a+1][(2*b+1 > 4) ? 4 : 2*b+1]
                                       : CF[2*a+1][2*b];
                    if (b < nx) fma4(acc, w, p[b*CQ]);
                }
            }
        }
    } else {
        const int ny = 3 - py;
        #pragma unroll
        for (int a = 0; a < 3; a++) {
            if (a >= ny) break;
            const int i = i0 + a;
            if ((unsigned)i >= (unsigned)Sl) continue;
            const int ky = 2*a + py;
            #pragma unroll
            for (int b = 0; b < 3; b++) {
                if (b >= nx) break;
                const int jj = j0 + b;
                if ((unsigned)jj >= (unsigned)Sl) continue;
                fma4(acc, c_f[ky][2*b + px], lo[(i*Sl + jj)*CQ + c4]);
            }
        }
    }

    const size_t idx = (((size_t)n*S + y)*S + x)*CQ + c4;
    const float4 iv = ((const float4*)img_of<L>())[idx];
    float4 outv;
    outv.x = iv.x - 4.f*acc.x; outv.y = iv.y - 4.f*acc.y;
    outv.z = iv.z - 4.f*acc.z; outv.w = iv.w - 4.f*acc.w;
    ((float4*)hi_of<L>())[idx] = outv;
}

// ---------------------------------------------------------------------------
// Sample + reduce, smem-windowed. block = (o-half, n), 512 threads.
// ---------------------------------------------------------------------------
__device__ __forceinline__ const float* level_gptr(int l) {
    switch (l) {
        case 0: return g_hi0;
        case 1: return g_hi1;
        case 2: return g_hi2;
        case 3: return g_hi3;
        default: return g_lo3;
    }
}

#define OHALF 2048
__global__ __launch_bounds__(512) void k_sample2(const float* __restrict__ grid,
                                                 const float* __restrict__ bias,
                                                 float* __restrict__ out) {
    constexpr int SSv [5] = {128, 64, 32, 16, 8};
    constexpr int CAPS[5] = {16, 12, 8, 6, 4};
    constexpr int WOFF[5] = {0, 256*32, 400*32, 464*32, 500*32};   // floats
    extern __shared__ float win[];                                  // 516*32 floats

    __shared__ float s_red[16][4];
    __shared__ float s_mm[4];       // minx, maxx, miny, maxy
    __shared__ int   s_org[5][2];
    __shared__ int   s_fb[5];

    const int n     = blockIdx.y;
    const int obase = blockIdx.x * OHALF;
    const int tid   = threadIdx.x;
    const int lane  = tid & 31;
    const int warp  = tid >> 5;

    // -- phase 1: block min/max of clipped grid coords --
    float mnx = 2.f, mxx = -2.f, mny = 2.f, mxy = -2.f;
    for (int i = tid; i < OHALF; i += 512) {
        const int o = obase + i;
        const float xs = fminf(fmaxf(grid[2*o    ], -1.f), 1.f);
        const float ys = fminf(fmaxf(grid[2*o + 1], -1.f), 1.f);
        mnx = fminf(mnx, xs); mxx = fmaxf(mxx, xs);
        mny = fminf(mny, ys); mxy = fmaxf(mxy, ys);
    }
    #pragma unroll
    for (int off = 16; off; off >>= 1) {
        mnx = fminf(mnx, __shfl_xor_sync(0xFFFFFFFFu, mnx, off));
        mxx = fmaxf(mxx, __shfl_xor_sync(0xFFFFFFFFu, mxx, off));
        mny = fminf(mny, __shfl_xor_sync(0xFFFFFFFFu, mny, off));
        mxy = fmaxf(mxy, __shfl_xor_sync(0xFFFFFFFFu, mxy, off));
    }
    if (lane == 0) {
        s_red[warp][0] = mnx; s_red[warp][1] = mxx;
        s_red[warp][2] = mny; s_red[warp][3] = mxy;
    }
    __syncthreads();
    if (warp == 0) {
        float a = (lane < 16) ? s_red[lane][0] :  2.f;
        float b = (lane < 16) ? s_red[lane][1] : -2.f;
        float c = (lane < 16) ? s_red[lane][2] :  2.f;
        float d = (lane < 16) ? s_red[lane][3] : -2.f;
        #pragma unroll
        for (int off = 8; off; off >>= 1) {
            a = fminf(a, __shfl_xor_sync(0xFFFFFFFFu, a, off));
            b = fmaxf(b, __shfl_xor_sync(0xFFFFFFFFu, b, off));
            c = fminf(c, __shfl_xor_sync(0xFFFFFFFFu, c, off));
            d = fmaxf(d, __shfl_xor_sync(0xFFFFFFFFu, d, off));
        }
        if (lane == 0) { s_mm[0] = a; s_mm[1] = b; s_mm[2] = c; s_mm[3] = d; }
    }
    __syncthreads();

    // -- phase 2: per-level window origin + fallback flag --
    if (tid < 5) {
        const int S = SSv[tid], CAP = CAPS[tid];
        const float fxmin = ((s_mm[0] + 1.f)*S - 1.f)*0.5f;
        const float fxmax = ((s_mm[1] + 1.f)*S - 1.f)*0.5f;
        const float fymin = ((s_mm[2] + 1.f)*S - 1.f)*0.5f;
        const float fymax = ((s_mm[3] + 1.f)*S - 1.f)*0.5f;
        const int xlo = max(0, (int)floorf(fxmin));
        const int xhi = min(S - 1, (int)floorf(fxmax) + 1);
        const int ylo = max(0, (int)floorf(fymin));
        const int yhi = min(S - 1, (int)floorf(fymax) + 1);
        s_fb[tid] = ((xhi - xlo + 1) > CAP) || ((yhi - ylo + 1) > CAP);
        s_org[tid][0] = min(max(xlo, 0), S - CAP);
        s_org[tid][1] = min(max(ylo, 0), S - CAP);
    }
    __syncthreads();

    // -- phase 3: load windows into smem (float4, coalesced) --
    {
        #pragma unroll
        for (int l = 0; l < 5; l++) {
            const int S = SSv[l], CAP = CAPS[l];
            const int wx0 = s_org[l][0], wy0 = s_org[l][1];
            const float4* src = (const float4*)level_gptr(l) + (size_t)n * S * S * 8;
            float4* dst = (float4*)(win + WOFF[l]);
            const int total = CAP * CAP * 8;
            for (int idx = tid; idx < total; idx += 512) {
                const int c4 = idx & 7;
                const int p  = idx >> 3;
                const int xx = p % CAP, yy = p / CAP;
                dst[idx] = src[((wy0 + yy)*S + (wx0 + xx))*8 + c4];
            }
        }
    }
    __syncthreads();

    // -- phase 4: sample + weighted reduce --
    for (int oi = warp; oi < OHALF; oi += 16) {
        const int o = obase + oi;
        const float xs = fminf(fmaxf(grid[2*o    ], -1.f), 1.f);
        const float ys = fminf(fmaxf(grid[2*o + 1], -1.f), 1.f);
        const float* ft = g_featT + (size_t)o*160 + lane;
        float acc = 0.f;

        #pragma unroll
        for (int l = 0; l < 5; l++) {
            const int S = SSv[l], CAP = CAPS[l];
            const float fx = ((xs + 1.f)*S - 1.f)*0.5f;
            const float fy = ((ys + 1.f)*S - 1.f)*0.5f;
            const float x0f = floorf(fx), y0f = floorf(fy);
            const float wx = fx - x0f, wy = fy - y0f;
            const int x0 = (int)x0f, y0 = (int)y0f;
            const float fv = ft[l*32];
            const int wx0 = s_org[l][0], wy0 = s_org[l][1];
            const float* W = win + WOFF[l];
            const bool fb = (s_fb[l] != 0);
            float lacc = 0.f;

            #pragma unroll
            for (int cy = 0; cy < 2; cy++) {
                #pragma unroll
                for (int cx = 0; cx < 2; cx++) {
                    const int xc = x0 + cx, yc = y0 + cy;
                    const float wgt = (cx ? wx : 1.f - wx) * (cy ? wy : 1.f - wy);
                    const int lx = xc - wx0, ly = yc - wy0;
                    if (!fb && (unsigned)lx < (unsigned)CAP && (unsigned)ly < (unsigned)CAP) {
                        lacc = fmaf(wgt, W[(ly*CAP + lx)*CH + lane], lacc);
                    } else if ((unsigned)xc < (unsigned)S && (unsigned)yc < (unsigned)S) {
                        lacc = fmaf(wgt,
                            level_gptr(l)[(((size_t)n*S + yc)*S + xc)*CH + lane], lacc);
                    }
                }
            }
            acc = fmaf(lacc, fv, acc);
        }
        #pragma unroll
        for (int off = 16; off; off >>= 1)
            acc += __shfl_xor_sync(0xFFFFFFFFu, acc, off);
        if (lane == 0)
            out[(size_t)n*OD + o] = acc + bias[o];
    }
}

// ---------------------------------------------------------------------------
extern "C" void kernel_launch(void* const* d_in, const int* in_sizes, int n_in,
                              void* d_out, int out_size) {
    const float* x    = (const float*)d_in[0];
    const float* grid = (const float*)d_in[1];
    const float* feat = (const float*)d_in[2];
    const float* bias = (const float*)d_in[3];
    float* out = (float*)d_out;

    const dim3 bT(32, 8);
    const dim3 bP(8, 32);
    const int SMEM = 516 * 32 * sizeof(float);   // 66048 B

    static bool attr_set = false;
    if (!attr_set) {
        cudaFuncSetAttribute(k_sample2, cudaFuncAttributeMaxDynamicSharedMemorySize, SMEM);
        attr_set = true;
    }

    k_transpose<<<dim3(PIX/32, NB), bT>>>(x);
    k_featT    <<<dim3(OD/32, 5),   bT>>>(feat);

    k_down4<0><<<dim3(2, 64, NB), bP>>>();
    k_hi4  <0><<<dim3(4,128, NB), bP>>>();
    k_down4<1><<<dim3(1, 32, NB), bP>>>();
    k_hi4  <1><<<dim3(2, 64, NB), bP>>>();
    k_down4<2><<<dim3(1, 16, NB), bP>>>();
    k_hi4  <2><<<dim3(1, 32, NB), bP>>>();
    k_down4<3><<<dim3(1,  8, NB), bP>>>();
    k_hi4  <3><<<dim3(1, 16, NB), bP>>>();

    k_sample2<<<dim3(OD/OHALF, NB), 512, SMEM>>>(grid, bias, out);
}

// round 8
// speedup vs baseline: 1.3334x; 1.0732x over previous
#include <cuda_runtime.h>
#include <cuda_bf16.h>
#include <cstdint>

#define NB 64
#define CH 32
#define OD 4096
#define PIX (128*128)

// Gaussian 5x5 — __device__ constexpr folds to immediates on compile-time index
__device__ constexpr float CF[5][5] = {
    {0.003765f, 0.015019f, 0.023792f, 0.015019f, 0.003765f},
    {0.015019f, 0.059912f, 0.094907f, 0.059912f, 0.015019f},
    {0.023792f, 0.094907f, 0.150342f, 0.094907f, 0.023792f},
    {0.015019f, 0.059912f, 0.094907f, 0.059912f, 0.015019f},
    {0.003765f, 0.015019f, 0.023792f, 0.015019f, 0.003765f}
};
__constant__ float c_f[5][5] = {
    {0.003765f, 0.015019f, 0.023792f, 0.015019f, 0.003765f},
    {0.015019f, 0.059912f, 0.094907f, 0.059912f, 0.015019f},
    {0.023792f, 0.094907f, 0.150342f, 0.094907f, 0.023792f},
    {0.015019f, 0.059912f, 0.094907f, 0.059912f, 0.015019f},
    {0.003765f, 0.015019f, 0.023792f, 0.015019f, 0.003765f}
};

// NHWC lo-pyramid scratch + transposed features
static __device__ __align__(256) float g_lo0 [(size_t)NB*64*64*CH];
static __device__ __align__(256) float g_lo1 [(size_t)NB*32*32*CH];
static __device__ __align__(256) float g_lo2 [(size_t)NB*16*16*CH];
static __device__ __align__(256) float g_lo3 [(size_t)NB* 8* 8*CH];
static __device__ __align__(256) float g_featT[(size_t)OD*160];

__device__ __forceinline__ void fma4(float4& a, float w, float4 v) {
    a.x = fmaf(w, v.x, a.x); a.y = fmaf(w, v.y, a.y);
    a.z = fmaf(w, v.z, a.z); a.w = fmaf(w, v.w, a.w);
}

// ---------------------------------------------------------------------------
// feat (160, OD) -> featT (OD, 160)
// ---------------------------------------------------------------------------
__global__ __launch_bounds__(256) void k_featT(const float* __restrict__ feat) {
    __shared__ float tile[32][33];
    const int o0 = blockIdx.x * 32;
    const int r0 = blockIdx.y * 32;
    const int tx = threadIdx.x, ty = threadIdx.y;
    #pragma unroll
    for (int r = ty; r < 32; r += 8)
        if (r0 + r < 160) tile[r][tx] = feat[(size_t)(r0 + r)*OD + o0 + tx];
    __syncthreads();
    #pragma unroll
    for (int r = ty; r < 32; r += 8)
        if (r0 + tx < 160) g_featT[(size_t)(o0 + r)*160 + r0 + tx] = tile[tx][r];
}

// ---------------------------------------------------------------------------
// Fused level-0 downsample: x NCHW -> lo0 NHWC (5x5 @ even pixels, zero-pad)
// block 256; tile: 8 output rows x 16 output cols x 32 ch
// stage: 19 rows x 36 cols x 32 ch in smem (layout [rs][c], stride 33)
// ---------------------------------------------------------------------------
#define D0_R 19
#define D0_C 36
__global__ __launch_bounds__(256) void k_down0(const float* __restrict__ xg) {
    extern __shared__ float sx[];   // (D0_R*D0_C)*33 floats
    const int n  = blockIdx.z;
    const int i0 = blockIdx.y * 8;
    const int j0 = blockIdx.x * 16;
    const int tid = threadIdx.x;
    const int trow = 2*i0 - 2;
    const int tcol = 2*j0 - 2;

    for (int e = tid; e < 32*D0_R*D0_C; e += 256) {
        const int c  = e / (D0_R*D0_C);
        const int rs = e % (D0_R*D0_C);
        const int r = rs / D0_C, s = rs % D0_C;
        const int t = trow + r, u = tcol + s;
        float v = 0.f;
        if ((unsigned)t < 128u && (unsigned)u < 128u)
            v = xg[(((size_t)(n*CH + c))*128 + t)*128 + u];
        sx[rs*33 + c] = v;
    }
    __syncthreads();

    const int ch = tid & 31;
    const int q0 = tid >> 5;          // 0..7
    #pragma unroll
    for (int k = 0; k < 16; k++) {
        const int q  = q0 + k*8;      // 0..127
        const int jj = q & 15, ii = q >> 4;
        float acc = 0.f;
        #pragma unroll
        for (int ky = 0; ky < 5; ky++)
            #pragma unroll
            for (int kx = 0; kx < 5; kx++)
                acc = fmaf(CF[ky][kx], sx[((2*ii+ky)*D0_C + 2*jj+kx)*33 + ch], acc);
        g_lo0[(((size_t)n*64 + i0+ii)*64 + j0+jj)*32 + ch] = acc;
    }
}

// ---------------------------------------------------------------------------
template<int L> __device__ __forceinline__ const float* img_of() {
    if (L == 1) return g_lo0;
    if (L == 2) return g_lo1;
    return g_lo2;
}
template<int L> __device__ __forceinline__ float* lo_of() {
    if (L == 1) return g_lo1;
    if (L == 2) return g_lo2;
    return g_lo3;
}

// ---------------------------------------------------------------------------
// Downsample levels 1..3 (float4 over channels, NHWC->NHWC)
// ---------------------------------------------------------------------------
template<int L>
__global__ __launch_bounds__(256) void k_down4() {
    constexpr int S  = 128 >> L;
    constexpr int Sl = S / 2;
    const int c4 = threadIdx.x;
    const int j  = blockIdx.x * 32 + threadIdx.y;
    const int i  = blockIdx.y;
    const int n  = blockIdx.z;
    if (j >= Sl) return;

    const float4* img = (const float4*)img_of<L>() + (size_t)n * S * S * (CH/4);
    float4 acc = make_float4(0.f, 0.f, 0.f, 0.f);

    const bool interior = (i >= 1) & (i <= Sl-2) & (j >= 1) & (j <= Sl-2);
    if (interior) {
        const float4* p = img + ((2*i-2)*S + (2*j-2))*(CH/4) + c4;
        #pragma unroll
        for (int ky = 0; ky < 5; ky++)
            #pragma unroll
            for (int kx = 0; kx < 5; kx++)
                fma4(acc, CF[ky][kx], p[(ky*S + kx)*(CH/4)]);
    } else {
        #pragma unroll
        for (int ky = 0; ky < 5; ky++) {
            const int t = 2*i + ky - 2;
            if ((unsigned)t >= (unsigned)S) continue;
            #pragma unroll
            for (int kx = 0; kx < 5; kx++) {
                const int s = 2*j + kx - 2;
                if ((unsigned)s >= (unsigned)S) continue;
                fma4(acc, c_f[ky][kx], img[(t*S + s)*(CH/4) + c4]);
            }
        }
    }
    ((float4*)lo_of<L>())[(((size_t)n*Sl + i)*Sl + j)*(CH/4) + c4] = acc;
}

// ---------------------------------------------------------------------------
// Upconv (lhs-dilated conv) read from global lo, bounds-checked
// ---------------------------------------------------------------------------
__device__ __forceinline__ float upconv_g(const float* __restrict__ lo, int Sl,
                                          int n, int yc, int xc, int ch) {
    const int py = yc & 1, px = xc & 1;
    const int i0 = (yc - 2 + py) >> 1;
    const int j0 = (xc - 2 + px) >> 1;
    const float* base = lo + (size_t)n * Sl * Sl * CH + ch;
    float acc = 0.f;
    #pragma unroll
    for (int a = 0; a < 3; a++) {
        if (a >= 3 - py) break;
        const int i = i0 + a;
        if ((unsigned)i >= (unsigned)Sl) continue;
        #pragma unroll
        for (int b = 0; b < 3; b++) {
            if (b >= 3 - px) break;
            const int j = j0 + b;
            if ((unsigned)j >= (unsigned)Sl) continue;
            acc += c_f[2*a+py][2*b+px] * base[(i*Sl + j)*CH];
        }
    }
    return acc;
}

__device__ __forceinline__ const float* lo_gptr(int l) {
    switch (l) {
        case 0: return g_lo0;
        case 1: return g_lo1;
        case 2: return g_lo2;
        default: return g_lo3;
    }
}

// Fallback: compute a single hi (or lo3) value from globals
template<int L>
__device__ __forceinline__ float sample_fallback(const float* __restrict__ xg,
                                                 int n, int yc, int xc, int ch) {
    if (L == 4) {
        return g_lo3[(((size_t)n*8 + yc)*8 + xc)*CH + ch];
    } else {
        constexpr int S = 128 >> L;
        float img;
        if (L == 0) img = xg[(((size_t)(n*CH + ch))*128 + yc)*128 + xc];
        else        img = lo_gptr(L-1)[(((size_t)n*S + yc)*S + xc)*CH + ch];
        return img - 4.f * upconv_g(lo_gptr(L), S/2, n, yc, xc, ch);
    }
}

// ---------------------------------------------------------------------------
// Sampler: builds hi windows in smem on the fly, then samples + reduces.
// block = (o-half, n), 512 threads. Window layout [pix][ch] stride 33.
// ---------------------------------------------------------------------------
#define OHALF 2048
__global__ __launch_bounds__(512) void k_sample2(const float* __restrict__ xg,
                                                 const float* __restrict__ grid,
                                                 const float* __restrict__ bias,
                                                 float* __restrict__ out) {
    constexpr int SSv [5] = {128, 64, 32, 16, 8};
    constexpr int CAPS[5] = {16, 12, 8, 6, 4};
    constexpr int WOFF[5] = {0, 256*33, 400*33, 464*33, 500*33};
    extern __shared__ float win[];                 // 516*33 floats

    __shared__ float s_red[16][4];
    __shared__ float s_mm[4];
    __shared__ int   s_org[5][2];
    __shared__ int   s_fb[5];

    const int n     = blockIdx.y;
    const int obase = blockIdx.x * OHALF;
    const int tid   = threadIdx.x;
    const int lane  = tid & 31;
    const int warp  = tid >> 5;

    // -- phase 1: block min/max of clipped grid coords --
    float mnx = 2.f, mxx = -2.f, mny = 2.f, mxy = -2.f;
    for (int i = tid; i < OHALF; i += 512) {
        const int o = obase + i;
        const float xs = fminf(fmaxf(grid[2*o    ], -1.f), 1.f);
        const float ys = fminf(fmaxf(grid[2*o + 1], -1.f), 1.f);
        mnx = fminf(mnx, xs); mxx = fmaxf(mxx, xs);
        mny = fminf(mny, ys); mxy = fmaxf(mxy, ys);
    }
    #pragma unroll
    for (int off = 16; off; off >>= 1) {
        mnx = fminf(mnx, __shfl_xor_sync(0xFFFFFFFFu, mnx, off));
        mxx = fmaxf(mxx, __shfl_xor_sync(0xFFFFFFFFu, mxx, off));
        mny = fminf(mny, __shfl_xor_sync(0xFFFFFFFFu, mny, off));
        mxy = fmaxf(mxy, __shfl_xor_sync(0xFFFFFFFFu, mxy, off));
    }
    if (lane == 0) {
        s_red[warp][0] = mnx; s_red[warp][1] = mxx;
        s_red[warp][2] = mny; s_red[warp][3] = mxy;
    }
    __syncthreads();
    if (warp == 0) {
        float a = (lane < 16) ? s_red[lane][0] :  2.f;
        float b = (lane < 16) ? s_red[lane][1] : -2.f;
        float c = (lane < 16) ? s_red[lane][2] :  2.f;
        float d = (lane < 16) ? s_red[lane][3] : -2.f;
        #pragma unroll
        for (int off = 8; off; off >>= 1) {
            a = fminf(a, __shfl_xor_sync(0xFFFFFFFFu, a, off));
            b = fmaxf(b, __shfl_xor_sync(0xFFFFFFFFu, b, off));
            c = fminf(c, __shfl_xor_sync(0xFFFFFFFFu, c, off));
            d = fmaxf(d, __shfl_xor_sync(0xFFFFFFFFu, d, off));
        }
        if (lane == 0) { s_mm[0] = a; s_mm[1] = b; s_mm[2] = c; s_mm[3] = d; }
    }
    __syncthreads();

    // -- phase 2: per-level window origin + fallback flag --
    if (tid < 5) {
        const int S = SSv[tid], CAP = CAPS[tid];
        const float fxmin = ((s_mm[0] + 1.f)*S - 1.f)*0.5f;
        const float fxmax = ((s_mm[1] + 1.f)*S - 1.f)*0.5f;
        const float fymin = ((s_mm[2] + 1.f)*S - 1.f)*0.5f;
        const float fymax = ((s_mm[3] + 1.f)*S - 1.f)*0.5f;
        const int xlo = max(0, (int)floorf(fxmin));
        const int xhi = min(S - 1, (int)floorf(fxmax) + 1);
        const int ylo = max(0, (int)floorf(fymin));
        const int yhi = min(S - 1, (int)floorf(fymax) + 1);
        s_fb[tid] = ((xhi - xlo + 1) > CAP) || ((yhi - ylo + 1) > CAP);
        s_org[tid][0] = min(max(xlo, 0), S - CAP);
        s_org[tid][1] = min(max(ylo, 0), S - CAP);
    }
    __syncthreads();

    // -- phase 3: build hi windows in smem --
    // L0 pass A: x window (NCHW, coalesced along x)
    {
        const int wx0 = s_org[0][0], wy0 = s_org[0][1];
        for (int e = tid; e < 32*256; e += 512) {
            const int c = e >> 8, p = e & 255;
            const int yy = p >> 4, xx = p & 15;
            win[p*33 + c] = xg[(((size_t)(n*CH + c))*128 + wy0 + yy)*128 + wx0 + xx];
        }
    }
    __syncthreads();
    // L0 pass B: subtract 4*upconv(lo0)
    {
        const int wx0 = s_org[0][0], wy0 = s_org[0][1];
        for (int e = tid; e < 256*32; e += 512) {
            const int ch = e & 31, p = e >> 5;
            const int yy = p >> 4, xx = p & 15;
            const float up = upconv_g(g_lo0, 64, n, wy0 + yy, wx0 + xx, ch);
            win[p*33 + ch] -= 4.f * up;
        }
    }
    // L1..L3: hi = lo_{l-1} - 4*upconv(lo_l)
    #pragma unroll
    for (int l = 1; l < 4; l++) {
        const int S = SSv[l], CAP = CAPS[l];
        const int wx0 = s_org[l][0], wy0 = s_org[l][1];
        const float* imgp = (l == 1) ? g_lo0 : (l == 2) ? g_lo1 : g_lo2;
        const float* lop  = (l == 1) ? g_lo1 : (l == 2) ? g_lo2 : g_lo3;
        float* W = win + WOFF[l];
        for (int e = tid; e < CAP*CAP*32; e += 512) {
            const int ch = e & 31, p = e >> 5;
            const int yy = p / CAP, xx = p % CAP;
            const int yc = wy0 + yy, xc = wx0 + xx;
            const float img = imgp[(((size_t)n*S + yc)*S + xc)*CH + ch];
            const float up  = upconv_g(lop, S/2, n, yc, xc, ch);
            W[p*33 + ch] = img - 4.f * up;
        }
    }
    // L4: lo3 window
    {
        const int wx0 = s_org[4][0], wy0 = s_org[4][1];
        float* W = win + WOFF[4];
        for (int e = tid; e < 16*32; e += 512) {
            const int ch = e & 31, p = e >> 5;
            const int yy = p >> 2, xx = p & 3;
            W[p*33 + ch] = g_lo3[(((size_t)n*8 + wy0 + yy)*8 + wx0 + xx)*CH + ch];
        }
    }
    __syncthreads();

    // -- phase 4: sample + weighted reduce --
    for (int oi = warp; oi < OHALF; oi += 16) {
        const int o = obase + oi;
        const float xs = fminf(fmaxf(grid[2*o    ], -1.f), 1.f);
        const float ys = fminf(fmaxf(grid[2*o + 1], -1.f), 1.f);
        const float* ft = g_featT + (size_t)o*160 + lane;
        float acc = 0.f;

        #pragma unroll
        for (int l = 0; l < 5; l++) {
            const int S = SSv[l], CAP = CAPS[l];
            const float fx = ((xs + 1.f)*S - 1.f)*0.5f;
            const float fy = ((ys + 1.f)*S - 1.f)*0.5f;
            const float x0f = floorf(fx), y0f = floorf(fy);
            const float wx = fx - x0f, wy = fy - y0f;
            const int x0 = (int)x0f, y0 = (int)y0f;
            const float fv = ft[l*32];
            const int wx0 = s_org[l][0], wy0 = s_org[l][1];
            const float* W = win + WOFF[l];
            const bool fb = (s_fb[l] != 0);
            float lacc = 0.f;

            #pragma unroll
            for (int cy = 0; cy < 2; cy++) {
                #pragma unroll
                for (int cx = 0; cx < 2; cx++) {
                    const int xc = x0 + cx, yc = y0 + cy;
                    const float wgt = (cx ? wx : 1.f - wx) * (cy ? wy : 1.f - wy);
                    const int lx = xc - wx0, ly = yc - wy0;
                    if (!fb && (unsigned)lx < (unsigned)CAP && (unsigned)ly < (unsigned)CAP) {
                        lacc = fmaf(wgt, W[(ly*CAP + lx)*33 + lane], lacc);
                    } else if ((unsigned)xc < (unsigned)S && (unsigned)yc < (unsigned)S) {
                        float v;
                        switch (l) {
                            case 0: v = sample_fallback<0>(xg, n, yc, xc, lane); break;
                            case 1: v = sample_fallback<1>(xg, n, yc, xc, lane); break;
                            case 2: v = sample_fallback<2>(xg, n, yc, xc, lane); break;
                            case 3: v = sample_fallback<3>(xg, n, yc, xc, lane); break;
                            default: v = sample_fallback<4>(xg, n, yc, xc, lane); break;
                        }
                        lacc = fmaf(wgt, v, lacc);
                    }
                }
            }
            acc = fmaf(lacc, fv, acc);
        }
        #pragma unroll
        for (int off = 16; off; off >>= 1)
            acc += __shfl_xor_sync(0xFFFFFFFFu, acc, off);
        if (lane == 0)
            out[(size_t)n*OD + o] = acc + bias[o];
    }
}

// ---------------------------------------------------------------------------
extern "C" void kernel_launch(void* const* d_in, const int* in_sizes, int n_in,
                              void* d_out, int out_size) {
    const float* x    = (const float*)d_in[0];
    const float* grid = (const float*)d_in[1];
    const float* feat = (const float*)d_in[2];
    const float* bias = (const float*)d_in[3];
    float* out = (float*)d_out;

    const dim3 bT(32, 8);
    const dim3 bP(8, 32);
    const int SMEM_D0 = (D0_R*D0_C) * 33 * sizeof(float);  // 90288 B
    const int SMEM_SP = 516 * 33 * sizeof(float);          // 68112 B

    static bool attr_set = false;
    if (!attr_set) {
        cudaFuncSetAttribute(k_down0,   cudaFuncAttributeMaxDynamicSharedMemorySize, SMEM_D0);
        cudaFuncSetAttribute(k_sample2, cudaFuncAttributeMaxDynamicSharedMemorySize, SMEM_SP);
        attr_set = true;
    }

    k_featT<<<dim3(OD/32, 5), bT>>>(feat);

    k_down0   <<<dim3(4, 8, NB), 256, SMEM_D0>>>(x);
    k_down4<1><<<dim3(1, 32, NB), bP>>>();
    k_down4<2><<<dim3(1, 16, NB), bP>>>();
    k_down4<3><<<dim3(1,  8, NB), bP>>>();

    k_sample2<<<dim3(OD/OHALF, NB), 512, SMEM_SP>>>(x, grid, bias, out);
}